// round 4
// baseline (speedup 1.0000x reference)
#include <cuda_runtime.h>
#include <cstdint>

#define HDIM 64
#define NOBJ 25
#define ROWF 100          // floats per sample in canvas (25*4)
#define SAMPLES_PER_CTA 64
#define SMEM_BYTES (65536 + 17408 + 25600)   // Wq + h(64x68) + seq(64x25 float4) = 108544

// Device-global scratch (no allocations allowed)
__device__ int    g_Tmax;
__device__ float4 g_Wq[64 * 64];   // [k][j] = (W_i, W_f, W_g, W_o) at (row g*64+j, col k) of W_hh
__device__ float4 g_Aq[4 * 64];    // [d][j] = per-gate coefficient of x_d  (A = W_ih @ W_emb)
__device__ float4 g_Bq[64];        // [j]    = per-gate total bias (W_ih@b_emb + b_ih + b_hh)

// ---------------- f32x2 helpers (Blackwell packed fp32 FMA) ----------------
__device__ __forceinline__ unsigned long long pack2(float a, float b) {
    unsigned long long r;
    asm("mov.b64 %0, {%1, %2};" : "=l"(r) : "f"(a), "f"(b));
    return r;
}
__device__ __forceinline__ void unpack2(unsigned long long v, float& lo, float& hi) {
    asm("mov.b64 {%0, %1}, %2;" : "=f"(lo), "=f"(hi) : "l"(v));
}
__device__ __forceinline__ unsigned long long ffma2(unsigned long long a,
                                                    unsigned long long b,
                                                    unsigned long long c) {
#if defined(__CUDA_ARCH__) && (__CUDA_ARCH__ >= 1000)
    unsigned long long d;
    asm("fma.rn.f32x2 %0, %1, %2, %3;" : "=l"(d) : "l"(a), "l"(b), "l"(c));
    return d;
#else
    float alo, ahi, blo, bhi, clo, chi;
    unpack2(a, alo, ahi); unpack2(b, blo, bhi); unpack2(c, clo, chi);
    return pack2(fmaf(alo, blo, clo), fmaf(ahi, bhi, chi));
#endif
}

__device__ __forceinline__ float sigm(float x) {
    return __fdividef(1.0f, 1.0f + __expf(-x));
}
__device__ __forceinline__ float tanh_fast(float x) {
    return __fdividef(2.0f, 1.0f + __expf(-2.0f * x)) - 1.0f;
}

// ---------------- Kernel 0: fold Linear into LSTM input path, repack W_hh ----------------
__global__ void precompute_kernel(const float* __restrict__ W_emb, const float* __restrict__ b_emb,
                                  const float* __restrict__ W_ih,  const float* __restrict__ W_hh,
                                  const float* __restrict__ b_ih,  const float* __restrict__ b_hh) {
    const int tid = threadIdx.x;  // 256 threads
    if (tid == 0) g_Tmax = 0;     // reset max each launch (stream-ordered before count_kernel)

    // Repack W_hh (256,64) into gate-interleaved [k][j] float4
    for (int idx = tid; idx < 64 * 64; idx += 256) {
        const int k = idx >> 6, j = idx & 63;
        float4 w;
        w.x = W_hh[(0 * 64 + j) * 64 + k];
        w.y = W_hh[(1 * 64 + j) * 64 + k];
        w.z = W_hh[(2 * 64 + j) * 64 + k];
        w.w = W_hh[(3 * 64 + j) * 64 + k];
        g_Wq[idx] = w;
    }

    // A[r][d] = sum_k W_ih[r][k] * W_emb[k][d];  bias[r] = sum_k W_ih[r][k]*b_emb[k] + b_ih[r] + b_hh[r]
    if (tid < 64) {
        const int j = tid;
        float acc[4][5];
        #pragma unroll
        for (int g = 0; g < 4; g++)
            #pragma unroll
            for (int d = 0; d < 5; d++) acc[g][d] = 0.0f;
        for (int k = 0; k < 64; k++) {
            const float be = b_emb[k];
            #pragma unroll
            for (int g = 0; g < 4; g++) {
                const float wih = W_ih[(g * 64 + j) * 64 + k];
                #pragma unroll
                for (int d = 0; d < 4; d++) acc[g][d] = fmaf(wih, W_emb[k * 4 + d], acc[g][d]);
                acc[g][4] = fmaf(wih, be, acc[g][4]);
            }
        }
        #pragma unroll
        for (int d = 0; d < 4; d++)
            g_Aq[d * 64 + j] = make_float4(acc[0][d], acc[1][d], acc[2][d], acc[3][d]);
        g_Bq[j] = make_float4(acc[0][4] + b_ih[0 * 64 + j] + b_hh[0 * 64 + j],
                              acc[1][4] + b_ih[1 * 64 + j] + b_hh[1 * 64 + j],
                              acc[2][4] + b_ih[2 * 64 + j] + b_hh[2 * 64 + j],
                              acc[3][4] + b_ih[3 * 64 + j] + b_hh[3 * 64 + j]);
    }
}

// ---------------- Kernel 1: global T_max = max over batch of valid-object count ----------------
__global__ void count_kernel(const float* __restrict__ canvas, int B) {
    __shared__ int smax;
    if (threadIdx.x == 0) smax = 0;
    __syncthreads();

    const int warp = blockIdx.x * (blockDim.x >> 5) + (threadIdx.x >> 5);
    const int lane = threadIdx.x & 31;
    if (warp < B) {
        int valid = 0;
        if (lane < NOBJ) {
            const float4 v = *reinterpret_cast<const float4*>(canvas + (size_t)warp * ROWF + lane * 4);
            const float s = ((v.x + v.y) + v.z) + v.w;
            valid = (s >= 0.0f) ? 1 : 0;
        }
        const unsigned msk = __ballot_sync(0xFFFFFFFFu, valid);
        const int cnt = __popc(msk);
        if (lane == 0 && cnt > 0) atomicMax(&smax, cnt);
    }
    __syncthreads();
    if (threadIdx.x == 0 && smax > 0) atomicMax(&g_Tmax, smax);
}

// ---------------- Kernel 2: fused compaction + LSTM (64 samples per CTA) ----------------
// Thread layout: j = tid&63 (hidden unit), sg = tid>>6 (sample subgroup of 16 samples).
// Each thread keeps h,c for its 16 samples in registers; h is exchanged via smem each step.
// Inner matvec uses packed fma.rn.f32x2 over sample pairs; W duplicated into both halves.
__global__ void __launch_bounds__(256, 1) lstm_kernel(const float* __restrict__ canvas,
                                                      float* __restrict__ out, int B) {
    extern __shared__ char smem[];
    float4* sWq  = reinterpret_cast<float4*>(smem);                  // 64x64 float4 = 65536 B
    float*  sH   = reinterpret_cast<float*>(smem + 65536);           // [64][68] floats = 17408 B
    float4* sSeq = reinterpret_cast<float4*>(smem + 82944);          // [64][25] float4 = 25600 B

    const int tid     = threadIdx.x;
    const int j       = tid & 63;
    const int sg      = tid >> 6;       // 0..3
    const int sgBase  = sg * 16;
    const int ctaBase = blockIdx.x * SAMPLES_PER_CTA;

    // Load repacked W_hh into smem (coalesced)
    #pragma unroll
    for (int i = 0; i < 16; i++) sWq[tid + i * 256] = g_Wq[tid + i * 256];

    // Zero h buffer
    for (int i = tid; i < 64 * 68; i += 256) sH[i] = 0.0f;

    // Compaction: 8 warps, 8 samples each. Stable-compact valid rows, pad with -1.
    {
        const int w = tid >> 5, lane = tid & 31;
        #pragma unroll
        for (int m = 0; m < 8; m++) {
            const int s = w * 8 + m;
            const int b = ctaBase + s;
            float4 v = make_float4(-1.0f, -1.0f, -1.0f, -1.0f);
            int valid = 0;
            if (b < B && lane < NOBJ) {
                v = *reinterpret_cast<const float4*>(canvas + (size_t)b * ROWF + lane * 4);
                const float sum = ((v.x + v.y) + v.z) + v.w;
                valid = (sum >= 0.0f) ? 1 : 0;
            }
            const unsigned msk = __ballot_sync(0xFFFFFFFFu, valid);
            const int cnt = __popc(msk);
            if (lane < NOBJ) {
                if (valid) {
                    const int pos = __popc(msk & ((1u << lane) - 1u));
                    sSeq[s * NOBJ + pos] = v;
                }
                if (lane >= cnt) sSeq[s * NOBJ + lane] = make_float4(-1.0f, -1.0f, -1.0f, -1.0f);
            }
        }
    }

    // Hoist folded input coefficients into registers
    const float4 A0 = g_Aq[0 * 64 + j];
    const float4 A1 = g_Aq[1 * 64 + j];
    const float4 A2 = g_Aq[2 * 64 + j];
    const float4 A3 = g_Aq[3 * 64 + j];
    const float4 Bq = g_Bq[j];

    float h[16], c[16];
    #pragma unroll
    for (int m = 0; m < 16; m++) { h[m] = 0.0f; c[m] = 0.0f; }

    const int T = g_Tmax;
    __syncthreads();

    for (int t = 0; t < T; t++) {
        unsigned long long ai[8], af[8], ag[8], ao[8];

        // x-side: gate preactivation init from compacted (or pad) object features
        #pragma unroll
        for (int p = 0; p < 8; p++) {
            const float4 xa = sSeq[(sgBase + 2 * p) * NOBJ + t];
            const float4 xb = sSeq[(sgBase + 2 * p + 1) * NOBJ + t];
            const float i0 = fmaf(A3.x, xa.w, fmaf(A2.x, xa.z, fmaf(A1.x, xa.y, fmaf(A0.x, xa.x, Bq.x))));
            const float f0 = fmaf(A3.y, xa.w, fmaf(A2.y, xa.z, fmaf(A1.y, xa.y, fmaf(A0.y, xa.x, Bq.y))));
            const float g0 = fmaf(A3.z, xa.w, fmaf(A2.z, xa.z, fmaf(A1.z, xa.y, fmaf(A0.z, xa.x, Bq.z))));
            const float o0 = fmaf(A3.w, xa.w, fmaf(A2.w, xa.z, fmaf(A1.w, xa.y, fmaf(A0.w, xa.x, Bq.w))));
            const float i1 = fmaf(A3.x, xb.w, fmaf(A2.x, xb.z, fmaf(A1.x, xb.y, fmaf(A0.x, xb.x, Bq.x))));
            const float f1 = fmaf(A3.y, xb.w, fmaf(A2.y, xb.z, fmaf(A1.y, xb.y, fmaf(A0.y, xb.x, Bq.y))));
            const float g1 = fmaf(A3.z, xb.w, fmaf(A2.z, xb.z, fmaf(A1.z, xb.y, fmaf(A0.z, xb.x, Bq.z))));
            const float o1 = fmaf(A3.w, xb.w, fmaf(A2.w, xb.z, fmaf(A1.w, xb.y, fmaf(A0.w, xb.x, Bq.w))));
            ai[p] = pack2(i0, i1); af[p] = pack2(f0, f1);
            ag[p] = pack2(g0, g1); ao[p] = pack2(o0, o1);
        }

        // Recurrent matvec: gates += W_hh * h  (packed f32x2, 16 samples per thread)
        #pragma unroll 4
        for (int k = 0; k < 64; k++) {
            const float4 wv = sWq[k * 64 + j];
            const unsigned long long wi = pack2(wv.x, wv.x);
            const unsigned long long wf = pack2(wv.y, wv.y);
            const unsigned long long wg = pack2(wv.z, wv.z);
            const unsigned long long wo = pack2(wv.w, wv.w);
            const ulonglong2* hp = reinterpret_cast<const ulonglong2*>(sH + k * 68 + sgBase);
            #pragma unroll
            for (int q = 0; q < 4; q++) {
                const ulonglong2 h4 = hp[q];     // 4 samples per 16B broadcast load
                ai[2 * q]     = ffma2(wi, h4.x, ai[2 * q]);
                af[2 * q]     = ffma2(wf, h4.x, af[2 * q]);
                ag[2 * q]     = ffma2(wg, h4.x, ag[2 * q]);
                ao[2 * q]     = ffma2(wo, h4.x, ao[2 * q]);
                ai[2 * q + 1] = ffma2(wi, h4.y, ai[2 * q + 1]);
                af[2 * q + 1] = ffma2(wf, h4.y, af[2 * q + 1]);
                ag[2 * q + 1] = ffma2(wg, h4.y, ag[2 * q + 1]);
                ao[2 * q + 1] = ffma2(wo, h4.y, ao[2 * q + 1]);
            }
        }

        // Nonlinearity + state update (torch gate order i,f,g,o)
        #pragma unroll
        for (int p = 0; p < 8; p++) {
            float iv0, iv1, fv0, fv1, gv0, gv1, ov0, ov1;
            unpack2(ai[p], iv0, iv1); unpack2(af[p], fv0, fv1);
            unpack2(ag[p], gv0, gv1); unpack2(ao[p], ov0, ov1);
            const int m0 = 2 * p, m1 = 2 * p + 1;
            const float c0 = sigm(fv0) * c[m0] + sigm(iv0) * tanh_fast(gv0);
            c[m0] = c0; h[m0] = sigm(ov0) * tanh_fast(c0);
            const float c1 = sigm(fv1) * c[m1] + sigm(iv1) * tanh_fast(gv1);
            c[m1] = c1; h[m1] = sigm(ov1) * tanh_fast(c1);
        }

        __syncthreads();   // all reads of old h done
        #pragma unroll
        for (int q = 0; q < 4; q++) {
            *reinterpret_cast<float4*>(sH + j * 68 + sgBase + 4 * q) =
                make_float4(h[4 * q], h[4 * q + 1], h[4 * q + 2], h[4 * q + 3]);
        }
        __syncthreads();   // new h visible
    }

    // Final h write (coalesced: 64 consecutive units per sample across 2 warps)
    #pragma unroll
    for (int m = 0; m < 16; m++) {
        const int b = ctaBase + sgBase + m;
        if (b < B) out[(size_t)b * HDIM + j] = h[m];
    }
}

// ---------------- launch ----------------
extern "C" void kernel_launch(void* const* d_in, const int* in_sizes, int n_in,
                              void* d_out, int out_size) {
    const float* canvas = (const float*)d_in[0];
    const float* W_emb  = (const float*)d_in[1];
    const float* b_emb  = (const float*)d_in[2];
    const float* W_ih   = (const float*)d_in[3];
    const float* W_hh   = (const float*)d_in[4];
    const float* b_ih   = (const float*)d_in[5];
    const float* b_hh   = (const float*)d_in[6];
    float* out = (float*)d_out;

    const int B = in_sizes[0] / ROWF;

    cudaFuncSetAttribute(lstm_kernel, cudaFuncAttributeMaxDynamicSharedMemorySize, SMEM_BYTES);

    precompute_kernel<<<1, 256>>>(W_emb, b_emb, W_ih, W_hh, b_ih, b_hh);
    count_kernel<<<(B + 7) / 8, 256>>>(canvas, B);
    lstm_kernel<<<(B + SAMPLES_PER_CTA - 1) / SAMPLES_PER_CTA, 256, SMEM_BYTES>>>(canvas, out, B);
}

// round 6
// speedup vs baseline: 2.3556x; 2.3556x over previous
#include <cuda_runtime.h>
#include <cstdint>

#define NOBJ 25
#define ROWF 100          // floats per canvas row (25*4)
#define SPC  64           // samples per CTA (MMA M)
#define ASTR 72           // A-tile row stride in floats (K = 72)

__device__ int   g_Tmax;
__device__ float g_Bmat[256 * 72];   // folded weight matrix, gate-permuted rows, tf32-rounded

// ---------------- helpers ----------------
__device__ __forceinline__ uint32_t f2tf32(float x) {
    uint32_t r; asm("cvt.rna.tf32.f32 %0, %1;" : "=r"(r) : "f"(x)); return r;
}

__device__ __forceinline__ void mma8(float& d0, float& d1, float& d2, float& d3,
                                     uint32_t a0, uint32_t a1, uint32_t a2, uint32_t a3,
                                     uint32_t b0, uint32_t b1) {
    asm volatile("mma.sync.aligned.m16n8k8.row.col.f32.tf32.tf32.f32 "
                 "{%0,%1,%2,%3}, {%4,%5,%6,%7}, {%8,%9}, {%0,%1,%2,%3};"
                 : "+f"(d0), "+f"(d1), "+f"(d2), "+f"(d3)
                 : "r"(a0), "r"(a1), "r"(a2), "r"(a3), "r"(b0), "r"(b1));
}

__device__ __forceinline__ float sigm(float x) {
    return __fdividef(1.0f, 1.0f + __expf(-x));
}
__device__ __forceinline__ float tanh_fast(float x) {
    return __fdividef(2.0f, 1.0f + __expf(-2.0f * x)) - 1.0f;
}

// ---------------- Kernel 0: build folded, gate-permuted B matrix [256][72] ----------------
// n-row mapping: tile = n>>3 (8 cols per n8-tile), pair = (n&7)>>1, which = n&1.
//   unit u = ((tile>>1)<<2) + pair; gate = even tile ? (which?f:i) : (which?o:g)   [torch i,f,g,o]
// Row contents (K dim): [0..63] = W_hh[wr][k], [64..67] = (W_ih@W_emb)[wr][d],
//                       [68] = W_ih@b_emb + b_ih + b_hh, [69..71] = 0.   All tf32-rounded.
__global__ void precompute_kernel(const float* __restrict__ W_emb, const float* __restrict__ b_emb,
                                  const float* __restrict__ W_ih,  const float* __restrict__ W_hh,
                                  const float* __restrict__ b_ih,  const float* __restrict__ b_hh) {
    const int n = threadIdx.x;            // 256 threads, one B-row each
    if (n == 0) g_Tmax = 0;
    const int tile = n >> 3, pair = (n & 7) >> 1, which = n & 1;
    const int u = ((tile >> 1) << 2) + pair;
    const int gate = (tile & 1) ? (2 + which) : which;      // i=0,f=1,g=2,o=3
    const int wr = gate * 64 + u;

    float* dst = g_Bmat + n * 72;
    for (int k = 0; k < 64; k++)
        dst[k] = __uint_as_float(f2tf32(W_hh[wr * 64 + k]));

    float a0 = 0.f, a1 = 0.f, a2 = 0.f, a3 = 0.f, bias = 0.f;
    for (int k = 0; k < 64; k++) {
        const float wih = W_ih[wr * 64 + k];
        a0 = fmaf(wih, W_emb[k * 4 + 0], a0);
        a1 = fmaf(wih, W_emb[k * 4 + 1], a1);
        a2 = fmaf(wih, W_emb[k * 4 + 2], a2);
        a3 = fmaf(wih, W_emb[k * 4 + 3], a3);
        bias = fmaf(wih, b_emb[k], bias);
    }
    bias += b_ih[wr] + b_hh[wr];
    dst[64] = __uint_as_float(f2tf32(a0));
    dst[65] = __uint_as_float(f2tf32(a1));
    dst[66] = __uint_as_float(f2tf32(a2));
    dst[67] = __uint_as_float(f2tf32(a3));
    dst[68] = __uint_as_float(f2tf32(bias));
    dst[69] = 0.f; dst[70] = 0.f; dst[71] = 0.f;
}

// ---------------- Kernel 1: batch-wide max valid-object count ----------------
__global__ void count_kernel(const float* __restrict__ canvas, int B) {
    __shared__ int smax;
    if (threadIdx.x == 0) smax = 0;
    __syncthreads();
    const int warp = blockIdx.x * (blockDim.x >> 5) + (threadIdx.x >> 5);
    const int lane = threadIdx.x & 31;
    if (warp < B) {
        int valid = 0;
        if (lane < NOBJ) {
            const float4 v = *reinterpret_cast<const float4*>(canvas + (size_t)warp * ROWF + lane * 4);
            valid = (((v.x + v.y) + v.z) + v.w >= 0.0f) ? 1 : 0;
        }
        const unsigned msk = __ballot_sync(0xFFFFFFFFu, valid);
        if (lane == 0 && msk) atomicMax(&smax, __popc(msk));
    }
    __syncthreads();
    if (threadIdx.x == 0 && smax > 0) atomicMax(&g_Tmax, smax);
}

// ---------------- Kernel 2: tf32 mma.sync LSTM, 64 samples per CTA, 8 warps ----------------
// Warp w owns gate columns n in [w*32, w*32+32) = units [8w, 8w+8).
// Thread (gid = lane>>2, tig = lane&3): samples s0 = mt*16+gid, s1 = s0+8 per m-tile;
// units u0 = 8w+tig, u1 = u0+4.  All 4 gates of each (s,u) land in-thread by B permutation.
__global__ void __launch_bounds__(256, 1) lstm_kernel(const float* __restrict__ canvas,
                                                      float* __restrict__ out, int B) {
    __shared__ float  sA[SPC * ASTR];         // 18432 B : [h(64) | x(4) | 1 | pad][64 samples]
    __shared__ float4 sSeq[SPC * NOBJ];       // 25600 B : compacted sequences

    const int tid  = threadIdx.x;
    const int w    = tid >> 5, lane = tid & 31;
    const int gid  = lane >> 2, tig = lane & 3;
    const int u0   = w * 8 + tig, u1 = u0 + 4;
    const int ctaBase = blockIdx.x * SPC;

    // Zero A tile
    for (int i = tid; i < SPC * ASTR; i += 256) sA[i] = 0.0f;
    __syncthreads();

    // Constant-1 column (col 68) for the bias row of B
    if (tid < SPC) sA[tid * ASTR + 68] = 1.0f;

    // Compaction: each warp stable-compacts 8 samples; pad rows = full -1 vectors
    #pragma unroll
    for (int m = 0; m < 8; m++) {
        const int s = w * 8 + m;
        const int b = ctaBase + s;
        float4 v = make_float4(-1.f, -1.f, -1.f, -1.f);
        int valid = 0;
        if (b < B && lane < NOBJ) {
            v = *reinterpret_cast<const float4*>(canvas + (size_t)b * ROWF + lane * 4);
            valid = (((v.x + v.y) + v.z) + v.w >= 0.0f) ? 1 : 0;
        }
        const unsigned msk = __ballot_sync(0xFFFFFFFFu, valid);
        const int cnt = __popc(msk);
        if (lane < NOBJ) {
            if (valid) sSeq[s * NOBJ + __popc(msk & ((1u << lane) - 1u))] = v;
            if (lane >= cnt) sSeq[s * NOBJ + lane] = make_float4(-1.f, -1.f, -1.f, -1.f);
        }
    }

    // B fragments: persistent in registers for the whole CTA lifetime (72 regs)
    uint32_t bf[9][4][2];
    {
        const int nw = w * 32;
        #pragma unroll
        for (int kc = 0; kc < 9; kc++)
            #pragma unroll
            for (int nt = 0; nt < 4; nt++) {
                const float* bp = g_Bmat + (nw + nt * 8 + gid) * 72 + kc * 8 + tig;
                bf[kc][nt][0] = __float_as_uint(bp[0]);
                bf[kc][nt][1] = __float_as_uint(bp[4]);
            }
    }

    float c_[16], hreg[16];
    #pragma unroll
    for (int i = 0; i < 16; i++) { c_[i] = 0.f; hreg[i] = 0.f; }

    const int T = g_Tmax;
    __syncthreads();

    for (int t = 0; t < T; t++) {
        // x_t columns (64..67), tf32-rounded; one writer thread per sample
        if (tid < SPC) {
            const float4 x = sSeq[tid * NOBJ + t];
            float4 xr;
            xr.x = __uint_as_float(f2tf32(x.x));
            xr.y = __uint_as_float(f2tf32(x.y));
            xr.z = __uint_as_float(f2tf32(x.z));
            xr.w = __uint_as_float(f2tf32(x.w));
            *reinterpret_cast<float4*>(sA + tid * ASTR + 64) = xr;
        }
        __syncthreads();   // h (prev step) + x visible to all warps

        float acc[4][4][4];
        #pragma unroll
        for (int mt = 0; mt < 4; mt++)
            #pragma unroll
            for (int nt = 0; nt < 4; nt++)
                #pragma unroll
                for (int e = 0; e < 4; e++) acc[mt][nt][e] = 0.f;

        #pragma unroll
        for (int kc = 0; kc < 9; kc++) {
            uint32_t af[4][4];
            #pragma unroll
            for (int mt = 0; mt < 4; mt++) {
                const float* p0 = sA + (mt * 16 + gid) * ASTR + kc * 8 + tig;
                const float* p1 = p0 + 8 * ASTR;
                af[mt][0] = __float_as_uint(p0[0]);
                af[mt][1] = __float_as_uint(p1[0]);
                af[mt][2] = __float_as_uint(p0[4]);
                af[mt][3] = __float_as_uint(p1[4]);
            }
            #pragma unroll
            for (int mt = 0; mt < 4; mt++)
                #pragma unroll
                for (int nt = 0; nt < 4; nt++)
                    mma8(acc[mt][nt][0], acc[mt][nt][1], acc[mt][nt][2], acc[mt][nt][3],
                         af[mt][0], af[mt][1], af[mt][2], af[mt][3],
                         bf[kc][nt][0], bf[kc][nt][1]);
        }
        __syncthreads();   // all A reads done before epilogue rewrites h

        // Epilogue: 16 (sample, unit) LSTM updates per thread, h -> A tile (tf32)
        #pragma unroll
        for (int mt = 0; mt < 4; mt++) {
            const int s0 = mt * 16 + gid;
            #pragma unroll
            for (int q = 0; q < 4; q++) {
                // q: 0 -> (s0,u0), 1 -> (s0+8,u0), 2 -> (s0,u1), 3 -> (s0+8,u1)
                const int ntA = (q >> 1) * 2;        // 0 or 2 : (i,f) tile
                const int e   = (q & 1) * 2;         // 0 or 2 : row select
                const float iv = acc[mt][ntA][e + 0];
                const float fv = acc[mt][ntA][e + 1];
                const float gv = acc[mt][ntA + 1][e + 0];
                const float ov = acc[mt][ntA + 1][e + 1];
                const int ci = mt * 4 + q;
                const float cn = sigm(fv) * c_[ci] + sigm(iv) * tanh_fast(gv);
                c_[ci] = cn;
                const float hn = sigm(ov) * tanh_fast(cn);
                hreg[ci] = hn;
                const int s = s0 + (q & 1) * 8;
                const int u = (q >> 1) ? u1 : u0;
                sA[s * ASTR + u] = __uint_as_float(f2tf32(hn));
            }
        }
        // next iteration's top __syncthreads orders these writes before the MMA reads
    }

    // Stage fp32 h into A tile, then coalesced global write
    __syncthreads();
    #pragma unroll
    for (int mt = 0; mt < 4; mt++) {
        const int s0 = mt * 16 + gid;
        #pragma unroll
        for (int q = 0; q < 4; q++) {
            const int s = s0 + (q & 1) * 8;
            const int u = (q >> 1) ? u1 : u0;
            sA[s * ASTR + u] = hreg[mt * 4 + q];
        }
    }
    __syncthreads();
    for (int i = tid; i < SPC * 16; i += 256) {       // 16 float4 per sample
        const int s = i >> 4, q = i & 15;
        const int b = ctaBase + s;
        if (b < B) {
            const float4 v = *reinterpret_cast<const float4*>(sA + s * ASTR + q * 4);
            *reinterpret_cast<float4*>(out + (size_t)b * 64 + q * 4) = v;
        }
    }
}

// ---------------- launch ----------------
extern "C" void kernel_launch(void* const* d_in, const int* in_sizes, int n_in,
                              void* d_out, int out_size) {
    const float* canvas = (const float*)d_in[0];
    const float* W_emb  = (const float*)d_in[1];
    const float* b_emb  = (const float*)d_in[2];
    const float* W_ih   = (const float*)d_in[3];
    const float* W_hh   = (const float*)d_in[4];
    const float* b_ih   = (const float*)d_in[5];
    const float* b_hh   = (const float*)d_in[6];
    float* out = (float*)d_out;

    const int B = in_sizes[0] / ROWF;

    precompute_kernel<<<1, 256>>>(W_emb, b_emb, W_ih, W_hh, b_ih, b_hh);
    count_kernel<<<(B + 7) / 8, 256>>>(canvas, B);
    lstm_kernel<<<(B + SPC - 1) / SPC, 256>>>(canvas, out, B);
}

// round 7
// speedup vs baseline: 2.5420x; 1.0791x over previous
#include <cuda_runtime.h>
#include <cstdint>

#define NOBJ 25
#define ROWF 100          // floats per canvas row (25*4)
#define SPC  64           // samples per CTA (MMA M)
#define ASTR 76           // A-tile row stride in floats (conflict-free: 12*gid+tig distinct mod 32)

// dynamic smem layout (floats / bytes)
#define AFLOATS (SPC * ASTR)                  // 4864 floats per buffer
#define SMEM_TOTAL (2 * AFLOATS * 4 + SPC * NOBJ * 16)   // 38912 + 25600 = 64512 B

__device__ int   g_Tmax;
__device__ float g_Bmat[256 * 72];   // folded weight matrix, gate-permuted rows, tf32-rounded

// ---------------- helpers ----------------
__device__ __forceinline__ uint32_t f2tf32(float x) {
    uint32_t r; asm("cvt.rna.tf32.f32 %0, %1;" : "=r"(r) : "f"(x)); return r;
}

__device__ __forceinline__ void mma8(float& d0, float& d1, float& d2, float& d3,
                                     uint32_t a0, uint32_t a1, uint32_t a2, uint32_t a3,
                                     uint32_t b0, uint32_t b1) {
    asm volatile("mma.sync.aligned.m16n8k8.row.col.f32.tf32.tf32.f32 "
                 "{%0,%1,%2,%3}, {%4,%5,%6,%7}, {%8,%9}, {%0,%1,%2,%3};"
                 : "+f"(d0), "+f"(d1), "+f"(d2), "+f"(d3)
                 : "r"(a0), "r"(a1), "r"(a2), "r"(a3), "r"(b0), "r"(b1));
}

__device__ __forceinline__ float tanhapx(float x) {
    float y; asm("tanh.approx.f32 %0, %1;" : "=f"(y) : "f"(x)); return y;
}
__device__ __forceinline__ float sigm_t(float x) {
    return fmaf(tanhapx(0.5f * x), 0.5f, 0.5f);
}

// ---------------- Kernel 0: build folded, gate-permuted B matrix [256][72] ----------------
// n-row mapping: tile = n>>3, pair = (n&7)>>1, which = n&1.
//   unit u = ((tile>>1)<<2) + pair; gate = even tile ? (which?f:i) : (which?o:g)   [torch i,f,g,o]
// Row contents (K): [0..63]=W_hh[wr][k], [64..67]=(W_ih@W_emb)[wr][d],
//                   [68]=W_ih@b_emb+b_ih+b_hh, [69..71]=0.  All tf32-rounded.
__global__ void precompute_kernel(const float* __restrict__ W_emb, const float* __restrict__ b_emb,
                                  const float* __restrict__ W_ih,  const float* __restrict__ W_hh,
                                  const float* __restrict__ b_ih,  const float* __restrict__ b_hh) {
    const int n = threadIdx.x;            // 256 threads, one B-row each
    if (n == 0) g_Tmax = 0;
    const int tile = n >> 3, pair = (n & 7) >> 1, which = n & 1;
    const int u = ((tile >> 1) << 2) + pair;
    const int gate = (tile & 1) ? (2 + which) : which;      // i=0,f=1,g=2,o=3
    const int wr = gate * 64 + u;

    float* dst = g_Bmat + n * 72;
    for (int k = 0; k < 64; k++)
        dst[k] = __uint_as_float(f2tf32(W_hh[wr * 64 + k]));

    float a0 = 0.f, a1 = 0.f, a2 = 0.f, a3 = 0.f, bias = 0.f;
    for (int k = 0; k < 64; k++) {
        const float wih = W_ih[wr * 64 + k];
        a0 = fmaf(wih, W_emb[k * 4 + 0], a0);
        a1 = fmaf(wih, W_emb[k * 4 + 1], a1);
        a2 = fmaf(wih, W_emb[k * 4 + 2], a2);
        a3 = fmaf(wih, W_emb[k * 4 + 3], a3);
        bias = fmaf(wih, b_emb[k], bias);
    }
    bias += b_ih[wr] + b_hh[wr];
    dst[64] = __uint_as_float(f2tf32(a0));
    dst[65] = __uint_as_float(f2tf32(a1));
    dst[66] = __uint_as_float(f2tf32(a2));
    dst[67] = __uint_as_float(f2tf32(a3));
    dst[69] = 0.f; dst[70] = 0.f; dst[71] = 0.f;
    dst[68] = __uint_as_float(f2tf32(bias));
}

// ---------------- Kernel 1: batch-wide max valid-object count ----------------
__global__ void count_kernel(const float* __restrict__ canvas, int B) {
    __shared__ int smax;
    if (threadIdx.x == 0) smax = 0;
    __syncthreads();
    const int warp = blockIdx.x * (blockDim.x >> 5) + (threadIdx.x >> 5);
    const int lane = threadIdx.x & 31;
    if (warp < B) {
        int valid = 0;
        if (lane < NOBJ) {
            const float4 v = *reinterpret_cast<const float4*>(canvas + (size_t)warp * ROWF + lane * 4);
            valid = (((v.x + v.y) + v.z) + v.w >= 0.0f) ? 1 : 0;
        }
        const unsigned msk = __ballot_sync(0xFFFFFFFFu, valid);
        if (lane == 0 && msk) atomicMax(&smax, __popc(msk));
    }
    __syncthreads();
    if (threadIdx.x == 0 && smax > 0) atomicMax(&g_Tmax, smax);
}

// ---------------- Kernel 2: tf32 mma.sync LSTM, 64 samples/CTA, double-buffered A ----------------
// Warp w owns gate columns [w*32, w*32+32) = units [8w, 8w+8).
// Thread (gid=lane>>2, tig=lane&3): samples mt*16+gid, +8; units u0=8w+tig, u1=u0+4.
__global__ void __launch_bounds__(256, 1) lstm_kernel(const float* __restrict__ canvas,
                                                      float* __restrict__ out, int B) {
    extern __shared__ float smf[];
    float*  sAbuf[2] = { smf, smf + AFLOATS };
    float4* sSeq = reinterpret_cast<float4*>(smf + 2 * AFLOATS);

    const int tid  = threadIdx.x;
    const int w    = tid >> 5, lane = tid & 31;
    const int gid  = lane >> 2, tig = lane & 3;
    const int u0   = w * 8 + tig, u1 = u0 + 4;
    const int ctaBase = blockIdx.x * SPC;

    // Zero both A buffers; set bias column (68) = 1 in both
    for (int i = tid; i < 2 * AFLOATS; i += 256) smf[i] = 0.0f;
    __syncthreads();
    if (tid < SPC) { sAbuf[0][tid * ASTR + 68] = 1.0f; sAbuf[1][tid * ASTR + 68] = 1.0f; }

    // Compaction: each warp stable-compacts 8 samples; pads are full -1 vectors
    #pragma unroll
    for (int m = 0; m < 8; m++) {
        const int s = w * 8 + m;
        const int b = ctaBase + s;
        float4 v = make_float4(-1.f, -1.f, -1.f, -1.f);
        int valid = 0;
        if (b < B && lane < NOBJ) {
            v = *reinterpret_cast<const float4*>(canvas + (size_t)b * ROWF + lane * 4);
            valid = (((v.x + v.y) + v.z) + v.w >= 0.0f) ? 1 : 0;
        }
        const unsigned msk = __ballot_sync(0xFFFFFFFFu, valid);
        const int cnt = __popc(msk);
        if (lane < NOBJ) {
            if (valid) sSeq[s * NOBJ + __popc(msk & ((1u << lane) - 1u))] = v;
            if (lane >= cnt) sSeq[s * NOBJ + lane] = make_float4(-1.f, -1.f, -1.f, -1.f);
        }
    }

    // Persistent B fragments (72 regs/thread)
    uint32_t bf[9][4][2];
    {
        const int nw = w * 32;
        #pragma unroll
        for (int kc = 0; kc < 9; kc++)
            #pragma unroll
            for (int nt = 0; nt < 4; nt++) {
                const float* bp = g_Bmat + (nw + nt * 8 + gid) * 72 + kc * 8 + tig;
                bf[kc][nt][0] = __float_as_uint(bp[0]);
                bf[kc][nt][1] = __float_as_uint(bp[4]);
            }
    }

    float c_[16], hreg[16];
    #pragma unroll
    for (int i = 0; i < 16; i++) { c_[i] = 0.f; hreg[i] = 0.f; }

    const int T = g_Tmax;
    __syncthreads();

    // x_0 into buffer 0 (tf32-rounded)
    if (tid < SPC) {
        const float4 x = sSeq[tid * NOBJ + 0];
        float4 xr;
        xr.x = __uint_as_float(f2tf32(x.x));
        xr.y = __uint_as_float(f2tf32(x.y));
        xr.z = __uint_as_float(f2tf32(x.z));
        xr.w = __uint_as_float(f2tf32(x.w));
        *reinterpret_cast<float4*>(sAbuf[0] + tid * ASTR + 64) = xr;
    }
    __syncthreads();

    for (int t = 0; t < T; t++) {
        float* sA  = sAbuf[t & 1];
        float* sAn = sAbuf[(t & 1) ^ 1];

        float acc[4][4][4];
        #pragma unroll
        for (int mt = 0; mt < 4; mt++)
            #pragma unroll
            for (int nt = 0; nt < 4; nt++)
                #pragma unroll
                for (int e = 0; e < 4; e++) acc[mt][nt][e] = 0.f;

        #pragma unroll
        for (int kc = 0; kc < 9; kc++) {
            uint32_t af[4][4];
            #pragma unroll
            for (int mt = 0; mt < 4; mt++) {
                const float* p0 = sA + (mt * 16 + gid) * ASTR + kc * 8 + tig;
                const float* p1 = p0 + 8 * ASTR;
                af[mt][0] = __float_as_uint(p0[0]);
                af[mt][1] = __float_as_uint(p1[0]);
                af[mt][2] = __float_as_uint(p0[4]);
                af[mt][3] = __float_as_uint(p1[4]);
            }
            #pragma unroll
            for (int mt = 0; mt < 4; mt++)
                #pragma unroll
                for (int nt = 0; nt < 4; nt++)
                    mma8(acc[mt][nt][0], acc[mt][nt][1], acc[mt][nt][2], acc[mt][nt][3],
                         af[mt][0], af[mt][1], af[mt][2], af[mt][3],
                         bf[kc][nt][0], bf[kc][nt][1]);
        }

        // Epilogue: 16 (sample,unit) updates; h -> NEXT buffer (tf32), no intra-step barrier
        #pragma unroll
        for (int mt = 0; mt < 4; mt++) {
            const int s0 = mt * 16 + gid;
            #pragma unroll
            for (int q = 0; q < 4; q++) {
                const int ntA = (q >> 1) * 2;        // (i,f) tile
                const int e   = (q & 1) * 2;         // row select
                const float iv = acc[mt][ntA][e + 0];
                const float fv = acc[mt][ntA][e + 1];
                const float gv = acc[mt][ntA + 1][e + 0];
                const float ov = acc[mt][ntA + 1][e + 1];
                const int ci = mt * 4 + q;
                const float cn = sigm_t(fv) * c_[ci] + sigm_t(iv) * tanhapx(gv);
                c_[ci] = cn;
                const float hn = sigm_t(ov) * tanhapx(cn);
                hreg[ci] = hn;
                const int s = s0 + (q & 1) * 8;
                const int u = (q >> 1) ? u1 : u0;
                sAn[s * ASTR + u] = __uint_as_float(f2tf32(hn));
            }
        }

        // x_{t+1} into next buffer
        if (t + 1 < T && tid < SPC) {
            const float4 x = sSeq[tid * NOBJ + t + 1];
            float4 xr;
            xr.x = __uint_as_float(f2tf32(x.x));
            xr.y = __uint_as_float(f2tf32(x.y));
            xr.z = __uint_as_float(f2tf32(x.z));
            xr.w = __uint_as_float(f2tf32(x.w));
            *reinterpret_cast<float4*>(sAn + tid * ASTR + 64) = xr;
        }

        __syncthreads();   // single barrier: next buffer fully built before next MMA
    }

    // Stage fp32 h into buffer 0, then coalesced global write
    #pragma unroll
    for (int mt = 0; mt < 4; mt++) {
        const int s0 = mt * 16 + gid;
        #pragma unroll
        for (int q = 0; q < 4; q++) {
            const int s = s0 + (q & 1) * 8;
            const int u = (q >> 1) ? u1 : u0;
            sAbuf[0][s * ASTR + u] = hreg[mt * 4 + q];
        }
    }
    __syncthreads();
    for (int i = tid; i < SPC * 16; i += 256) {       // 16 float4 per sample
        const int s = i >> 4, q = i & 15;
        const int b = ctaBase + s;
        if (b < B) {
            const float4 v = *reinterpret_cast<const float4*>(sAbuf[0] + s * ASTR + q * 4);
            *reinterpret_cast<float4*>(out + (size_t)b * 64 + q * 4) = v;
        }
    }
}

// ---------------- launch ----------------
extern "C" void kernel_launch(void* const* d_in, const int* in_sizes, int n_in,
                              void* d_out, int out_size) {
    const float* canvas = (const float*)d_in[0];
    const float* W_emb  = (const float*)d_in[1];
    const float* b_emb  = (const float*)d_in[2];
    const float* W_ih   = (const float*)d_in[3];
    const float* W_hh   = (const float*)d_in[4];
    const float* b_ih   = (const float*)d_in[5];
    const float* b_hh   = (const float*)d_in[6];
    float* out = (float*)d_out;

    const int B = in_sizes[0] / ROWF;

    cudaFuncSetAttribute(lstm_kernel, cudaFuncAttributeMaxDynamicSharedMemorySize, SMEM_TOTAL);

    precompute_kernel<<<1, 256>>>(W_emb, b_emb, W_ih, W_hh, b_ih, b_hh);
    count_kernel<<<(B + 7) / 8, 256>>>(canvas, B);
    lstm_kernel<<<(B + SPC - 1) / SPC, 256, SMEM_TOTAL>>>(canvas, out, B);
}

// round 10
// speedup vs baseline: 3.1321x; 1.2321x over previous
#include <cuda_runtime.h>
#include <cstdint>

#define NOBJ 25
#define ROWF 100          // floats per canvas row (25*4)
#define SPC  128          // samples per CTA (8 m-tiles)
#define ASTR 76           // row stride in floats (conflict-free ldmatrix)

// dynamic smem layout (floats): sB[256*76] | sA0[128*76] | sA1[128*76] | sSeq[128*25 float4]
#define SB_F   (256 * ASTR)              // 19456
#define SA_F   (SPC * ASTR)              // 9728
#define OFF_A0 SB_F
#define OFF_A1 (SB_F + SA_F)
#define OFF_SEQ (SB_F + 2 * SA_F)        // 38912 floats (byte 155648, 16B aligned)
#define SMEM_TOTAL ((OFF_SEQ + SPC * NOBJ * 4) * 4)   // 206848 B

__device__ int   g_Tmax;
__device__ float g_Bmat[256 * 72];   // folded weight matrix, gate-permuted rows, tf32-rounded

// ---------------- helpers ----------------
__device__ __forceinline__ uint32_t f2tf32(float x) {
    uint32_t r; asm("cvt.rna.tf32.f32 %0, %1;" : "=r"(r) : "f"(x)); return r;
}

__device__ __forceinline__ void mma8(float& d0, float& d1, float& d2, float& d3,
                                     uint32_t a0, uint32_t a1, uint32_t a2, uint32_t a3,
                                     uint32_t b0, uint32_t b1) {
    asm volatile("mma.sync.aligned.m16n8k8.row.col.f32.tf32.tf32.f32 "
                 "{%0,%1,%2,%3}, {%4,%5,%6,%7}, {%8,%9}, {%0,%1,%2,%3};"
                 : "+f"(d0), "+f"(d1), "+f"(d2), "+f"(d3)
                 : "r"(a0), "r"(a1), "r"(a2), "r"(a3), "r"(b0), "r"(b1));
}

__device__ __forceinline__ void ldm_x4(uint32_t& r0, uint32_t& r1, uint32_t& r2, uint32_t& r3,
                                       uint32_t addr) {
    asm volatile("ldmatrix.sync.aligned.m8n8.x4.shared.b16 {%0,%1,%2,%3}, [%4];"
                 : "=r"(r0), "=r"(r1), "=r"(r2), "=r"(r3) : "r"(addr));
}

__device__ __forceinline__ float tanhapx(float x) {
    float y; asm("tanh.approx.f32 %0, %1;" : "=f"(y) : "f"(x)); return y;
}
__device__ __forceinline__ float sigm_t(float x) {
    return fmaf(tanhapx(0.5f * x), 0.5f, 0.5f);
}

// ---------------- Kernel 0: folded, gate-permuted B matrix [256][72] ----------------
// n-row mapping: tile=n>>3, pair=(n&7)>>1, which=n&1; u=((tile>>1)<<2)+pair;
// gate = even tile ? (which?f:i) : (which?o:g)   [torch i,f,g,o]
__global__ void precompute_kernel(const float* __restrict__ W_emb, const float* __restrict__ b_emb,
                                  const float* __restrict__ W_ih,  const float* __restrict__ W_hh,
                                  const float* __restrict__ b_ih,  const float* __restrict__ b_hh) {
    const int n = threadIdx.x;            // 256 threads, one B-row each
    if (n == 0) g_Tmax = 0;
    const int tile = n >> 3, pair = (n & 7) >> 1, which = n & 1;
    const int u = ((tile >> 1) << 2) + pair;
    const int gate = (tile & 1) ? (2 + which) : which;
    const int wr = gate * 64 + u;

    float* dst = g_Bmat + n * 72;
    for (int k = 0; k < 64; k++)
        dst[k] = __uint_as_float(f2tf32(W_hh[wr * 64 + k]));

    float a0 = 0.f, a1 = 0.f, a2 = 0.f, a3 = 0.f, bias = 0.f;
    for (int k = 0; k < 64; k++) {
        const float wih = W_ih[wr * 64 + k];
        a0 = fmaf(wih, W_emb[k * 4 + 0], a0);
        a1 = fmaf(wih, W_emb[k * 4 + 1], a1);
        a2 = fmaf(wih, W_emb[k * 4 + 2], a2);
        a3 = fmaf(wih, W_emb[k * 4 + 3], a3);
        bias = fmaf(wih, b_emb[k], bias);
    }
    bias += b_ih[wr] + b_hh[wr];
    dst[64] = __uint_as_float(f2tf32(a0));
    dst[65] = __uint_as_float(f2tf32(a1));
    dst[66] = __uint_as_float(f2tf32(a2));
    dst[67] = __uint_as_float(f2tf32(a3));
    dst[68] = __uint_as_float(f2tf32(bias));
    dst[69] = 0.f; dst[70] = 0.f; dst[71] = 0.f;
}

// ---------------- Kernel 1: batch-wide max valid-object count ----------------
__global__ void count_kernel(const float* __restrict__ canvas, int B) {
    __shared__ int smax;
    if (threadIdx.x == 0) smax = 0;
    __syncthreads();
    const int warp = blockIdx.x * (blockDim.x >> 5) + (threadIdx.x >> 5);
    const int lane = threadIdx.x & 31;
    if (warp < B) {
        int valid = 0;
        if (lane < NOBJ) {
            const float4 v = *reinterpret_cast<const float4*>(canvas + (size_t)warp * ROWF + lane * 4);
            valid = (((v.x + v.y) + v.z) + v.w >= 0.0f) ? 1 : 0;
        }
        const unsigned msk = __ballot_sync(0xFFFFFFFFu, valid);
        if (lane == 0 && msk) atomicMax(&smax, __popc(msk));
    }
    __syncthreads();
    if (threadIdx.x == 0 && smax > 0) atomicMax(&g_Tmax, smax);
}

// ---------------- Kernel 2: tf32 mma.sync LSTM, 128 samples/CTA, 512 threads ----------------
// Warp w: col-group wg=w&7 (gate cols [32wg,32wg+32) = units [8wg,8wg+8)),
//         m-half mh=w>>3 (samples mh*64 .. mh*64+63, 4 m-tiles).
// Thread (gid=lane>>2, tig=lane&3): units u0=8wg+tig, u1=u0+4.
__global__ void __launch_bounds__(512, 1) lstm_kernel(const float* __restrict__ canvas,
                                                      float* __restrict__ out, int B) {
    extern __shared__ float smf[];
    float* sB = smf;
    float* sAbuf[2] = { smf + OFF_A0, smf + OFF_A1 };
    float4* sSeq = reinterpret_cast<float4*>(smf + OFF_SEQ);

    const int tid  = threadIdx.x;
    const int w    = tid >> 5, lane = tid & 31;
    const int wg   = w & 7, mh = w >> 3;
    const int gid  = lane >> 2, tig = lane & 3;
    const int u0   = wg * 8 + tig, u1 = u0 + 4;
    const int nw   = wg * 32;
    const int ctaBase = blockIdx.x * SPC;

    // ldmatrix lane addressing
    const int r8 = lane & 7;
    const int a_row = ((lane >> 3) & 1) * 8 + r8;    // A: row within m-tile
    const int a_col = (lane >> 4) * 4;               // A: tf32 col within k-chunk
    const int b_row = ((lane >> 4)) * 8 + r8;        // B: row within n-tile PAIR
    const int b_col = ((lane >> 3) & 1) * 4;         // B: tf32 col within k-chunk
    const uint32_t sBaddr = (uint32_t)__cvta_generic_to_shared(sB);
    const uint32_t sAaddr[2] = { (uint32_t)__cvta_generic_to_shared(sAbuf[0]),
                                 (uint32_t)__cvta_generic_to_shared(sAbuf[1]) };

    // Load B [256][72] -> sB [256][76] (tf32-rounded already)
    for (int i = tid; i < 256 * 72; i += 512) {
        const int n = i / 72, k = i - n * 72;
        sB[n * ASTR + k] = g_Bmat[i];
    }
    // Zero A buffers
    for (int i = tid; i < 2 * SA_F; i += 512) smf[OFF_A0 + i] = 0.0f;
    __syncthreads();
    if (tid < SPC) { sAbuf[0][tid * ASTR + 68] = 1.0f; sAbuf[1][tid * ASTR + 68] = 1.0f; }

    // Compaction: 16 warps x 8 samples, stable-compact, pad -1
    #pragma unroll
    for (int m = 0; m < 8; m++) {
        const int s = w * 8 + m;
        const int b = ctaBase + s;
        float4 v = make_float4(-1.f, -1.f, -1.f, -1.f);
        int valid = 0;
        if (b < B && lane < NOBJ) {
            v = *reinterpret_cast<const float4*>(canvas + (size_t)b * ROWF + lane * 4);
            valid = (((v.x + v.y) + v.z) + v.w >= 0.0f) ? 1 : 0;
        }
        const unsigned msk = __ballot_sync(0xFFFFFFFFu, valid);
        const int cnt = __popc(msk);
        if (lane < NOBJ) {
            if (valid) sSeq[s * NOBJ + __popc(msk & ((1u << lane) - 1u))] = v;
            if (lane >= cnt) sSeq[s * NOBJ + lane] = make_float4(-1.f, -1.f, -1.f, -1.f);
        }
    }

    float c_[16];
    #pragma unroll
    for (int i = 0; i < 16; i++) c_[i] = 0.f;

    const int T = g_Tmax;
    __syncthreads();

    // x_0 into buffer 0 (tf32-rounded)
    if (tid < SPC) {
        const float4 x = sSeq[tid * NOBJ + 0];
        float4 xr;
        xr.x = __uint_as_float(f2tf32(x.x));
        xr.y = __uint_as_float(f2tf32(x.y));
        xr.z = __uint_as_float(f2tf32(x.z));
        xr.w = __uint_as_float(f2tf32(x.w));
        *reinterpret_cast<float4*>(sAbuf[0] + tid * ASTR + 64) = xr;
    }
    __syncthreads();

    for (int t = 0; t < T; t++) {
        const uint32_t aBase = sAaddr[t & 1];
        float* sAn = sAbuf[(t & 1) ^ 1];
        const bool last = (t == T - 1);

        float acc[4][4][4];
        #pragma unroll
        for (int mt = 0; mt < 4; mt++)
            #pragma unroll
            for (int nt = 0; nt < 4; nt++)
                #pragma unroll
                for (int e = 0; e < 4; e++) acc[mt][nt][e] = 0.f;

        #pragma unroll
        for (int kc = 0; kc < 9; kc++) {
            uint32_t bfr[2][4];
            #pragma unroll
            for (int p = 0; p < 2; p++) {
                const uint32_t addr = sBaddr +
                    (((nw + p * 16 + b_row) * ASTR) + kc * 8 + b_col) * 4u;
                ldm_x4(bfr[p][0], bfr[p][1], bfr[p][2], bfr[p][3], addr);
            }
            uint32_t af[4][4];
            #pragma unroll
            for (int mt = 0; mt < 4; mt++) {
                const uint32_t addr = aBase +
                    (((mh * 64 + mt * 16 + a_row) * ASTR) + kc * 8 + a_col) * 4u;
                ldm_x4(af[mt][0], af[mt][1], af[mt][2], af[mt][3], addr);
            }
            #pragma unroll
            for (int mt = 0; mt < 4; mt++)
                #pragma unroll
                for (int nt = 0; nt < 4; nt++)
                    mma8(acc[mt][nt][0], acc[mt][nt][1], acc[mt][nt][2], acc[mt][nt][3],
                         af[mt][0], af[mt][1], af[mt][2], af[mt][3],
                         bfr[nt >> 1][(nt & 1) * 2], bfr[nt >> 1][(nt & 1) * 2 + 1]);
        }

        // Epilogue: 16 (sample,unit) updates; h -> NEXT buffer (tf32); final step -> gmem fp32
        #pragma unroll
        for (int mt = 0; mt < 4; mt++) {
            const int s0 = mh * 64 + mt * 16 + gid;
            #pragma unroll
            for (int q = 0; q < 4; q++) {
                const int ntA = (q >> 1) * 2;
                const int e   = (q & 1) * 2;
                const float iv = acc[mt][ntA][e + 0];
                const float fv = acc[mt][ntA][e + 1];
                const float gv = acc[mt][ntA + 1][e + 0];
                const float ov = acc[mt][ntA + 1][e + 1];
                const int ci = mt * 4 + q;
                const float cn = sigm_t(fv) * c_[ci] + sigm_t(iv) * tanhapx(gv);
                c_[ci] = cn;
                const float hn = sigm_t(ov) * tanhapx(cn);
                const int s = s0 + (q & 1) * 8;
                const int u = (q >> 1) ? u1 : u0;
                sAn[s * ASTR + u] = __uint_as_float(f2tf32(hn));
                if (last) {
                    const int b = ctaBase + s;
                    if (b < B) out[(size_t)b * 64 + u] = hn;
                }
            }
        }

        // x_{t+1} into next buffer
        if (t + 1 < T && tid < SPC) {
            const float4 x = sSeq[tid * NOBJ + t + 1];
            float4 xr;
            xr.x = __uint_as_float(f2tf32(x.x));
            xr.y = __uint_as_float(f2tf32(x.y));
            xr.z = __uint_as_float(f2tf32(x.z));
            xr.w = __uint_as_float(f2tf32(x.w));
            *reinterpret_cast<float4*>(sAn + tid * ASTR + 64) = xr;
        }

        __syncthreads();   // single barrier per step
    }

    // T == 0: no steps ran, h = 0 everywhere (out is poisoned -> must write)
    if (T == 0) {
        for (int i = tid; i < SPC * 16; i += 512) {
            const int s = i >> 4, q = i & 15;
            const int b = ctaBase + s;
            if (b < B)
                *reinterpret_cast<float4*>(out + (size_t)b * 64 + q * 4) =
                    make_float4(0.f, 0.f, 0.f, 0.f);
        }
    }
}

// ---------------- launch ----------------
extern "C" void kernel_launch(void* const* d_in, const int* in_sizes, int n_in,
                              void* d_out, int out_size) {
    const float* canvas = (const float*)d_in[0];
    const float* W_emb  = (const float*)d_in[1];
    const float* b_emb  = (const float*)d_in[2];
    const float* W_ih   = (const float*)d_in[3];
    const float* W_hh   = (const float*)d_in[4];
    const float* b_ih   = (const float*)d_in[5];
    const float* b_hh   = (const float*)d_in[6];
    float* out = (float*)d_out;

    const int B = in_sizes[0] / ROWF;

    cudaFuncSetAttribute(lstm_kernel, cudaFuncAttributeMaxDynamicSharedMemorySize, SMEM_TOTAL);

    precompute_kernel<<<1, 256>>>(W_emb, b_emb, W_ih, W_hh, b_ih, b_hh);
    count_kernel<<<(B + 7) / 8, 256>>>(canvas, B);
    lstm_kernel<<<(B + SPC - 1) / SPC, 512, SMEM_TOTAL>>>(canvas, out, B);
}